// round 13
// baseline (speedup 1.0000x reference)
#include <cuda_runtime.h>
#include <cuda_bf16.h>

// Problem constants (B=4, 96^3 vol, 4^3 patches, E=768)
#define TOKENS   13824
#define MASKN    10368
#define UNMASKN  3456
#define EDIM     768
#define KDIM     64
#define KPAIRS   96            // K' = 3*KDIM = 192 bf16 -> 96 bf16x2 pairs
#define KSTEPS   12
#define TT       16            // tokens per block
#define NTHREADS 384
#define UT       (UNMASKN / TT)   // 216
#define MT       (MASKN / TT)     // 648
#define BATCH    4
#define AROW     99            // padded A' row stride (uint32 words)
#define BROW     776           // padded B stage row stride (uint32 words)
#define LOG2_1E4 13.287712379549449f

// positional-encoding table
__device__ float g_pe[24][256];
// split weights, expanded K'=192, packed bf16x2 pairs: g_B2[p][e] = (B'[2p][e], B'[2p+1][e])
// B'[k'][e]: k'=3m+r, r==1 -> Wlo[m][e], else Whi[m][e]
__device__ unsigned int g_B2[KPAIRS][EDIM];

__device__ __forceinline__ unsigned int bf16pair(float lo, float hi) {
    __nv_bfloat162 h = __floats2bfloat162_rn(lo, hi);   // .x = lo half
    return *reinterpret_cast<unsigned int*>(&h);
}

__device__ __forceinline__ void mma_bf16(float* c,
    unsigned int a0, unsigned int a1, unsigned int a2, unsigned int a3,
    unsigned int b0, unsigned int b1) {
    asm volatile(
        "mma.sync.aligned.m16n8k16.row.col.f32.bf16.bf16.f32 "
        "{%0,%1,%2,%3}, {%4,%5,%6,%7}, {%8,%9}, {%0,%1,%2,%3};"
        : "+f"(c[0]), "+f"(c[1]), "+f"(c[2]), "+f"(c[3])
        : "r"(a0), "r"(a1), "r"(a2), "r"(a3), "r"(b0), "r"(b1));
}

// ONE init kernel (keeps launches/call at 2 so ncu lands on embed):
// blocks [0,24): pe table; [24,312): W split; [312,..): mask_idx tail.
__global__ __launch_bounds__(256)
void init_kernel(const float* __restrict__ W, const int* __restrict__ perm,
                 float* __restrict__ tail_out, int n_tail) {
    const int bi = blockIdx.x, tid = threadIdx.x;
    if (bi < 24) {
        const float invf = exp2f(-(float)(tid >> 1) * (LOG2_1E4 / 128.0f));
        float s, c;
        sincosf((float)bi * invf, &s, &c);
        g_pe[bi][tid] = (tid & 1) ? c : s;
    } else if (bi < 24 + 288) {
        const int idx = (bi - 24) * 256 + tid;
        const int p = idx / EDIM, e = idx % EDIM;
        float v[2];
        #pragma unroll
        for (int i = 0; i < 2; i++) {
            const int kp = 2 * p + i, m = kp / 3, r = kp - 3 * m;
            const float wv = W[m * EDIM + e];
            const float wh = __bfloat162float(__float2bfloat16_rn(wv));
            v[i] = (r == 1) ? (wv - wh) : wv;
        }
        g_B2[p][e] = bf16pair(v[0], v[1]);
    } else {
        const int i = (bi - 24 - 288) * 256 + tid;
        if (i < n_tail) tail_out[i] = (float)perm[i];
    }
}

// One block: 16 tokens x 768 dims, bf16-split tensor MMA, fused bias/pe/LN.
// 384 threads = 12 warps = 12 dim-groups (64 dims each), M=16 (one m-tile).
// Small CTA -> 2 blocks/SM: barriers + staging latency overlap across blocks.
// Blocks [0, 864): unmask per batch. Blocks [864, 1512): mask tokens once, written x4.
__global__ __launch_bounds__(NTHREADS, 2)
void embed_kernel(const float* __restrict__ x,
                  const float* __restrict__ bias,
                  const float* __restrict__ mtok,
                  const float* __restrict__ gamma,
                  const float* __restrict__ beta,
                  const int*   __restrict__ perm,
                  float* __restrict__ out)
{
    __shared__ __align__(16) unsigned int As[TT][AROW];   // A' packed bf16x2
    __shared__ __align__(16) unsigned int Bs[8][BROW];    // B' stage (one k-step)
    __shared__ int   sH[TT], sW[TT], sD[TT];
    __shared__ float redS[TT][13], redQ[TT][13];
    __shared__ float meanv[TT], rstdv[TT];

    const int tid  = threadIdx.x;
    const int lane = tid & 31;
    const int dg   = tid >> 5;       // warp = dim group (64 dims)
    const int g    = lane >> 2;      // row within m16 (0..7)
    const int tg   = lane & 3;       // thread in group

    const int bi = blockIdx.x;
    const bool is_mask = bi >= BATCH * UT;
    int b = 0, tile;
    if (!is_mask) { b = bi / UT; tile = bi % UT; }
    else          { tile = bi - BATCH * UT; }

    // ---- acc init with bias (c0,c1 = token g; c2,c3 = token g+8) ----
    const int ebase = dg * 64 + 2 * tg;
    float acc[8][4];
    #pragma unroll
    for (int j = 0; j < 8; j++) {
        const float2 bb = *(const float2*)(bias + ebase + 8 * j);
        acc[j][0] = bb.x; acc[j][1] = bb.y; acc[j][2] = bb.x; acc[j][3] = bb.y;
    }

    // B-stage addressing: 1536 uint4 chunks = 8 rows x 192; 4 chunks/thread.
    // chunk j of thread: row rbase+2j, col cfix  (384 = 2*192)
    const int rbase = tid / 192;
    const int cfix  = (tid % 192) * 4;

    // prologue: LDG for ks=0
    uint4 nb0 = __ldg((const uint4*)&g_B2[rbase + 0][cfix]);
    uint4 nb1 = __ldg((const uint4*)&g_B2[rbase + 2][cfix]);
    uint4 nb2 = __ldg((const uint4*)&g_B2[rbase + 4][cfix]);
    uint4 nb3 = __ldg((const uint4*)&g_B2[rbase + 6][cfix]);

    // ---- stage A': gather 16 patch rows, bf16-split, expand K'=192 ----
    if (tid < 256) {
        const int tok = tid & 15;
        const int seg = tid >> 4;     // 0..15, 4 k-values each
        const int m   = tile * TT + tok;
        const int s   = is_mask ? perm[m] : perm[MASKN + m];
        const int h = s / 576, wq = (s % 576) / 24, d = s % 24;
        if (seg == 0) { sH[tok] = h; sW[tok] = wq; sD[tok] = d; }
        float4 v;
        if (!is_mask) {
            const int i = seg >> 2, j = seg & 3;
            const size_t xi = (((size_t)(b * 96 + 4 * h + i)) * 96 + (4 * wq + j)) * 96 + 4 * d;
            v = *(const float4*)(x + xi);
        } else {
            v = *(const float4*)(mtok + (size_t)m * KDIM + seg * 4);
        }
        const float f0 = v.x, f1 = v.y, f2 = v.z, f3 = v.w;
        const float h0 = __bfloat162float(__float2bfloat16_rn(f0));
        const float h1 = __bfloat162float(__float2bfloat16_rn(f1));
        const float h2 = __bfloat162float(__float2bfloat16_rn(f2));
        const float h3 = __bfloat162float(__float2bfloat16_rn(f3));
        unsigned int* ar = &As[tok][6 * seg];
        ar[0] = bf16pair(f0,      f0);        // (Ah0, Ah0)
        ar[1] = bf16pair(f0 - h0, f1);        // (Al0, Ah1)
        ar[2] = bf16pair(f1,      f1 - h1);   // (Ah1, Al1)
        ar[3] = bf16pair(f2,      f2);        // (Ah2, Ah2)
        ar[4] = bf16pair(f2 - h2, f3);        // (Al2, Ah3)
        ar[5] = bf16pair(f3,      f3 - h3);   // (Ah3, Al3)
    }

    // commit B stage for ks=0
    *(uint4*)&Bs[rbase + 0][cfix] = nb0;
    *(uint4*)&Bs[rbase + 2][cfix] = nb1;
    *(uint4*)&Bs[rbase + 4][cfix] = nb2;
    *(uint4*)&Bs[rbase + 6][cfix] = nb3;
    __syncthreads();

    // ---- GEMM main loop: 12 k-steps; LDG(ks+1) in flight during MMA(ks) ----
    const int bcol = dg * 64 + g;
    #pragma unroll 1
    for (int ks = 0; ks < KSTEPS; ks++) {
        if (ks < KSTEPS - 1) {
            const unsigned int (*gb)[EDIM] = &g_B2[8 * (ks + 1)];
            nb0 = __ldg((const uint4*)&gb[rbase + 0][cfix]);
            nb1 = __ldg((const uint4*)&gb[rbase + 2][cfix]);
            nb2 = __ldg((const uint4*)&gb[rbase + 4][cfix]);
            nb3 = __ldg((const uint4*)&gb[rbase + 6][cfix]);
        }
        const unsigned int a0 = As[g][8 * ks + tg];
        const unsigned int a1 = As[g + 8][8 * ks + tg];
        const unsigned int a2 = As[g][8 * ks + tg + 4];
        const unsigned int a3 = As[g + 8][8 * ks + tg + 4];
        #pragma unroll
        for (int j = 0; j < 8; j++) {
            const unsigned int b0 = Bs[tg][bcol + 8 * j];
            const unsigned int b1 = Bs[tg + 4][bcol + 8 * j];
            mma_bf16(acc[j], a0, a1, a2, a3, b0, b1);
        }
        if (ks < KSTEPS - 1) {
            __syncthreads();
            *(uint4*)&Bs[rbase + 0][cfix] = nb0;
            *(uint4*)&Bs[rbase + 2][cfix] = nb1;
            *(uint4*)&Bs[rbase + 4][cfix] = nb2;
            *(uint4*)&Bs[rbase + 6][cfix] = nb3;
            __syncthreads();
        }
    }

    // ---- epilogue: + positional encoding, LN stats ----
    const int t0 = g, t1 = g + 8;
    const int* sposArr = (dg < 4) ? sH : (dg < 8) ? sW : sD;
    const int pos0 = sposArr[t0], pos1 = sposArr[t1];
    const int pecol = (dg & 3) * 64 + 2 * tg;

    float s0 = 0.f, q0 = 0.f, s1 = 0.f, q1 = 0.f;
    #pragma unroll
    for (int j = 0; j < 8; j++) {
        const float2 p0 = *(const float2*)&g_pe[pos0][pecol + 8 * j];
        const float2 p1 = *(const float2*)&g_pe[pos1][pecol + 8 * j];
        acc[j][0] += p0.x; acc[j][1] += p0.y;
        acc[j][2] += p1.x; acc[j][3] += p1.y;
        s0 += acc[j][0] + acc[j][1];
        q0 += acc[j][0] * acc[j][0] + acc[j][1] * acc[j][1];
        s1 += acc[j][2] + acc[j][3];
        q1 += acc[j][2] * acc[j][2] + acc[j][3] * acc[j][3];
    }
    #pragma unroll
    for (int off = 1; off <= 2; off <<= 1) {
        s0 += __shfl_xor_sync(0xffffffffu, s0, off);
        q0 += __shfl_xor_sync(0xffffffffu, q0, off);
        s1 += __shfl_xor_sync(0xffffffffu, s1, off);
        q1 += __shfl_xor_sync(0xffffffffu, q1, off);
    }
    if (tg == 0) {
        redS[t0][dg] = s0; redQ[t0][dg] = q0;
        redS[t1][dg] = s1; redQ[t1][dg] = q1;
    }
    __syncthreads();

    if (tid < TT) {
        float sm = 0.f, sq = 0.f;
        #pragma unroll
        for (int wi = 0; wi < 12; wi++) { sm += redS[tid][wi]; sq += redQ[tid][wi]; }
        const float mn = sm * (1.0f / (float)EDIM);
        const float vr = sq * (1.0f / (float)EDIM) - mn * mn;
        meanv[tid] = mn;
        rstdv[tid] = rsqrtf(vr + 0.001f);
    }
    __syncthreads();

    const float mn0 = meanv[t0], rs0 = rstdv[t0];
    const float mn1 = meanv[t1], rs1 = rstdv[t1];

    if (!is_mask) {
        float* o0 = out + ((size_t)b * TOKENS + (size_t)tile * TT + t0) * EDIM;
        float* o1 = out + ((size_t)b * TOKENS + (size_t)tile * TT + t1) * EDIM;
        #pragma unroll
        for (int j = 0; j < 8; j++) {
            const int e = ebase + 8 * j;
            const float2 gm = *(const float2*)(gamma + e);
            const float2 bt = *(const float2*)(beta + e);
            float2 r0, r1;
            r0.x = (acc[j][0] - mn0) * rs0 * gm.x + bt.x;
            r0.y = (acc[j][1] - mn0) * rs0 * gm.y + bt.y;
            r1.x = (acc[j][2] - mn1) * rs1 * gm.x + bt.x;
            r1.y = (acc[j][3] - mn1) * rs1 * gm.y + bt.y;
            *(float2*)(o0 + e) = r0;
            *(float2*)(o1 + e) = r1;
        }
    } else {
        float* o0 = out + ((size_t)UNMASKN + (size_t)tile * TT + t0) * EDIM;
        float* o1 = out + ((size_t)UNMASKN + (size_t)tile * TT + t1) * EDIM;
        const size_t bstride = (size_t)TOKENS * EDIM;
        #pragma unroll
        for (int j = 0; j < 8; j++) {
            const int e = ebase + 8 * j;
            const float2 gm = *(const float2*)(gamma + e);
            const float2 bt = *(const float2*)(beta + e);
            float2 r0, r1;
            r0.x = (acc[j][0] - mn0) * rs0 * gm.x + bt.x;
            r0.y = (acc[j][1] - mn0) * rs0 * gm.y + bt.y;
            r1.x = (acc[j][2] - mn1) * rs1 * gm.x + bt.x;
            r1.y = (acc[j][3] - mn1) * rs1 * gm.y + bt.y;
            #pragma unroll
            for (int bb = 0; bb < BATCH; bb++) {
                *(float2*)(o0 + bb * bstride + e) = r0;
                *(float2*)(o1 + bb * bstride + e) = r1;
            }
        }
    }
}

extern "C" void kernel_launch(void* const* d_in, const int* in_sizes, int n_in,
                              void* d_out, int out_size) {
    const float* x     = (const float*)d_in[0];
    const float* W     = (const float*)d_in[1];
    const float* bias  = (const float*)d_in[2];
    const float* mtok  = (const float*)d_in[3];
    const float* gamma = (const float*)d_in[4];
    const float* beta  = (const float*)d_in[5];
    const int*   perm  = (const int*)d_in[6];
    float* out = (float*)d_out;

    const long long main_elems = (long long)BATCH * TOKENS * EDIM;  // 42,467,328
    const long long extra = (long long)out_size - main_elems;       // expected 10368 (mask_idx)
    const int n_tail = extra > 0 ? (int)extra : 0;
    const int tail_blocks = (n_tail + 255) / 256;

    init_kernel<<<24 + 288 + tail_blocks, 256>>>(W, perm, out + main_elems, n_tail);

    embed_kernel<<<BATCH * UT + MT, NTHREADS>>>(x, bias, mtok, gamma, beta, perm, out);
}

// round 14
// speedup vs baseline: 1.0640x; 1.0640x over previous
#include <cuda_runtime.h>
#include <cuda_bf16.h>

// Problem constants (B=4, 96^3 vol, 4^3 patches, E=768)
#define TOKENS   13824
#define MASKN    10368
#define UNMASKN  3456
#define EDIM     768
#define KDIM     64
#define KPAIRS   96            // K' = 3*KDIM = 192 bf16 -> 96 bf16x2 pairs
#define KSTEPS   12
#define TT       48            // tokens per block (3 m16 bands)
#define NTHREADS 768
#define UT       (UNMASKN / TT)   // 72
#define MT       (MASKN / TT)     // 216
#define BATCH    4
#define AROW     100           // padded A' row stride (words): 8-row x 4-bank perfect
#define BROW     776           // padded B row stride (words): rows shift 8 banks
#define NJ       12            // n8 tiles per warp (96 dims)
#define STAGEB   (8 * BROW * 4)   // bytes per B stage = 24832
#define LOG2_1E4 13.287712379549449f

// dynamic smem layout (bytes)
#define AS_OFF   0                         // 48*100*4 = 19200
#define BS_OFF   19200                     // 3*24832 = 74496
#define SH_OFF   (BS_OFF + 3 * STAGEB)     // 93696
#define SW_OFF   (SH_OFF + 192)
#define SD_OFF   (SW_OFF + 192)
#define RS_OFF   (SD_OFF + 192)            // 48*9*4 = 1728
#define RQ_OFF   (RS_OFF + 1728)
#define MN_OFF   (RQ_OFF + 1728)           // 192
#define RV_OFF   (MN_OFF + 192)
#define SMEM_TOTAL (RV_OFF + 192)          // 98112

__device__ float g_pe[24][256];
// split weights, expanded K'=192, packed bf16x2 pairs: g_B2[p][e] = (B'[2p][e], B'[2p+1][e])
// B'[k'][e]: k'=3m+r, r==1 -> Wlo[m][e], else Whi[m][e]
__device__ __align__(16) unsigned int g_B2[KPAIRS][EDIM];

__device__ __forceinline__ unsigned int bf16pair(float lo, float hi) {
    __nv_bfloat162 h = __floats2bfloat162_rn(lo, hi);
    return *reinterpret_cast<unsigned int*>(&h);
}

__device__ __forceinline__ void mma_bf16(float* c,
    unsigned int a0, unsigned int a1, unsigned int a2, unsigned int a3,
    unsigned int b0, unsigned int b1) {
    asm volatile(
        "mma.sync.aligned.m16n8k16.row.col.f32.bf16.bf16.f32 "
        "{%0,%1,%2,%3}, {%4,%5,%6,%7}, {%8,%9}, {%0,%1,%2,%3};"
        : "+f"(c[0]), "+f"(c[1]), "+f"(c[2]), "+f"(c[3])
        : "r"(a0), "r"(a1), "r"(a2), "r"(a3), "r"(b0), "r"(b1));
}

__device__ __forceinline__ void cpa16(unsigned int dst, const void* src) {
    asm volatile("cp.async.cg.shared.global [%0], [%1], 16;" :: "r"(dst), "l"(src));
}

// ONE init kernel: blocks [0,24): pe table; [24,312): W split; [312,..): mask_idx tail.
__global__ __launch_bounds__(256)
void init_kernel(const float* __restrict__ W, const int* __restrict__ perm,
                 float* __restrict__ tail_out, int n_tail) {
    const int bi = blockIdx.x, tid = threadIdx.x;
    if (bi < 24) {
        const float invf = exp2f(-(float)(tid >> 1) * (LOG2_1E4 / 128.0f));
        float s, c;
        sincosf((float)bi * invf, &s, &c);
        g_pe[bi][tid] = (tid & 1) ? c : s;
    } else if (bi < 24 + 288) {
        const int idx = (bi - 24) * 256 + tid;
        const int p = idx / EDIM, e = idx % EDIM;
        float v[2];
        #pragma unroll
        for (int i = 0; i < 2; i++) {
            const int kp = 2 * p + i, m = kp / 3, r = kp - 3 * m;
            const float wv = W[m * EDIM + e];
            const float wh = __bfloat162float(__float2bfloat16_rn(wv));
            v[i] = (r == 1) ? (wv - wh) : wv;
        }
        g_B2[p][e] = bf16pair(v[0], v[1]);
    } else {
        const int i = (bi - 24 - 288) * 256 + tid;
        if (i < n_tail) tail_out[i] = (float)perm[i];
    }
}

// One block: 48 tokens x 768 dims, bf16-split tensor MMA, fused bias/pe/LN.
// B staged via 3-stage cp.async ring, ONE __syncthreads per k-step.
// 24 warps = 3 token-bands(16) x 8 dim-groups(96 dims).
// Blocks [0,288): unmask per batch. Blocks [288,504): mask tokens once, written x4.
__global__ __launch_bounds__(NTHREADS, 1)
void embed_kernel(const float* __restrict__ x,
                  const float* __restrict__ bias,
                  const float* __restrict__ mtok,
                  const float* __restrict__ gamma,
                  const float* __restrict__ beta,
                  const int*   __restrict__ perm,
                  float* __restrict__ out)
{
    extern __shared__ __align__(16) char smem[];
    unsigned int (*As)[AROW] = (unsigned int (*)[AROW])(smem + AS_OFF);
    int*   sH    = (int*)(smem + SH_OFF);
    int*   sW    = (int*)(smem + SW_OFF);
    int*   sD    = (int*)(smem + SD_OFF);
    float (*redS)[9] = (float (*)[9])(smem + RS_OFF);
    float (*redQ)[9] = (float (*)[9])(smem + RQ_OFF);
    float* meanv = (float*)(smem + MN_OFF);
    float* rstdv = (float*)(smem + RV_OFF);
    const unsigned int bs_base =
        (unsigned int)__cvta_generic_to_shared(smem + BS_OFF);

    const int tid  = threadIdx.x;
    const int lane = tid & 31;
    const int w    = tid >> 5;
    const int g    = lane >> 2;      // row within m16 (0..7)
    const int tg   = lane & 3;       // thread in group
    const int band = w >> 3;         // token band (0..2)
    const int dg   = w & 7;          // dim group (96 dims)

    const int bi = blockIdx.x;
    const bool is_mask = bi >= BATCH * UT;
    int b = 0, tile;
    if (!is_mask) { b = bi / UT; tile = bi % UT; }
    else          { tile = bi - BATCH * UT; }

    // ---- acc init with bias (c0,c1 = token t0; c2,c3 = token t1) ----
    const int ebase = dg * 96 + 2 * tg;
    float acc[NJ][4];
    #pragma unroll
    for (int j = 0; j < NJ; j++) {
        const float2 bb = *(const float2*)(bias + ebase + 8 * j);
        acc[j][0] = bb.x; acc[j][1] = bb.y; acc[j][2] = bb.x; acc[j][3] = bb.y;
    }

    // ---- B staging addresses: 1536 uint4 chunks/kstep, 2 per thread ----
    const int r0 = tid / 192,     c0 = (tid % 192) * 4;       // rows 0..3
    const int r1 = r0 + 4;                                    // rows 4..7
    const unsigned int d0 = (unsigned int)((r0 * BROW + c0) * 4);
    const unsigned int d1 = (unsigned int)((r1 * BROW + c0) * 4);

    // prologue: group 0 -> stage 0
    cpa16(bs_base + d0, &g_B2[r0][c0]);
    cpa16(bs_base + d1, &g_B2[r1][c0]);
    asm volatile("cp.async.commit_group;");

    // ---- stage A': 48 tokens x 16 segs = 768 threads, bf16-split, K'=192 ----
    {
        const int tok = tid % 48;
        const int seg = tid / 48;     // 0..15, 4 k-values each
        const int m   = tile * TT + tok;
        const int s   = is_mask ? perm[m] : perm[MASKN + m];
        const int h = s / 576, wq = (s % 576) / 24, d = s % 24;
        if (seg == 0) { sH[tok] = h; sW[tok] = wq; sD[tok] = d; }
        float4 v;
        if (!is_mask) {
            const int i = seg >> 2, j = seg & 3;
            const size_t xi = (((size_t)(b * 96 + 4 * h + i)) * 96 + (4 * wq + j)) * 96 + 4 * d;
            v = *(const float4*)(x + xi);
        } else {
            v = *(const float4*)(mtok + (size_t)m * KDIM + seg * 4);
        }
        const float f0 = v.x, f1 = v.y, f2 = v.z, f3 = v.w;
        const float h0 = __bfloat162float(__float2bfloat16_rn(f0));
        const float h1 = __bfloat162float(__float2bfloat16_rn(f1));
        const float h2 = __bfloat162float(__float2bfloat16_rn(f2));
        const float h3 = __bfloat162float(__float2bfloat16_rn(f3));
        unsigned int* ar = &As[tok][6 * seg];
        ar[0] = bf16pair(f0,      f0);        // (Ah0, Ah0)
        ar[1] = bf16pair(f0 - h0, f1);        // (Al0, Ah1)
        ar[2] = bf16pair(f1,      f1 - h1);   // (Ah1, Al1)
        ar[3] = bf16pair(f2,      f2);        // (Ah2, Ah2)
        ar[4] = bf16pair(f2 - h2, f3);        // (Al2, Ah3)
        ar[5] = bf16pair(f3,      f3 - h3);   // (Ah3, Al3)
    }

    // ---- GEMM main loop: 12 k-steps, 3-stage ring, 1 barrier per step ----
    const int t0 = band * 16 + g, t1 = t0 + 8;
    const int bcol = dg * 96 + g;
    #pragma unroll 1
    for (int ks = 0; ks < KSTEPS; ks++) {
        // refill group ks+1 into stage (ks+1)%3 (that stage was read 2 syncs ago)
        if (ks + 1 < KSTEPS) {
            const unsigned int sb = bs_base + ((ks + 1) % 3) * STAGEB;
            cpa16(sb + d0, &g_B2[8 * (ks + 1) + r0][c0]);
            cpa16(sb + d1, &g_B2[8 * (ks + 1) + r1][c0]);
            asm volatile("cp.async.commit_group;");
            asm volatile("cp.async.wait_group 1;");
        } else {
            asm volatile("cp.async.wait_group 0;");
        }
        __syncthreads();

        const unsigned int* Bst =
            (const unsigned int*)(smem + BS_OFF + (ks % 3) * STAGEB);
        const unsigned int a0 = As[t0][8 * ks + tg];
        const unsigned int a1 = As[t1][8 * ks + tg];
        const unsigned int a2 = As[t0][8 * ks + tg + 4];
        const unsigned int a3 = As[t1][8 * ks + tg + 4];
        #pragma unroll
        for (int j = 0; j < NJ; j++) {
            const unsigned int b0 = Bst[tg * BROW + bcol + 8 * j];
            const unsigned int b1 = Bst[(tg + 4) * BROW + bcol + 8 * j];
            mma_bf16(acc[j], a0, a1, a2, a3, b0, b1);
        }
    }

    // ---- epilogue: + positional encoding, LN stats ----
    float s0 = 0.f, q0 = 0.f, s1 = 0.f, q1 = 0.f;
    #pragma unroll
    for (int j = 0; j < NJ; j++) {
        const int ecol = dg * 96 + 8 * j;         // never crosses a 256 boundary mid-tile
        const int seg  = ecol >> 8;
        const int p0 = (seg == 0) ? sH[t0] : (seg == 1) ? sW[t0] : sD[t0];
        const int p1 = (seg == 0) ? sH[t1] : (seg == 1) ? sW[t1] : sD[t1];
        const int pc = (ecol & 255) + 2 * tg;
        const float2 pe0 = *(const float2*)&g_pe[p0][pc];
        const float2 pe1 = *(const float2*)&g_pe[p1][pc];
        acc[j][0] += pe0.x; acc[j][1] += pe0.y;
        acc[j][2] += pe1.x; acc[j][3] += pe1.y;
        s0 += acc[j][0] + acc[j][1];
        q0 += acc[j][0] * acc[j][0] + acc[j][1] * acc[j][1];
        s1 += acc[j][2] + acc[j][3];
        q1 += acc[j][2] * acc[j][2] + acc[j][3] * acc[j][3];
    }
    #pragma unroll
    for (int off = 1; off <= 2; off <<= 1) {
        s0 += __shfl_xor_sync(0xffffffffu, s0, off);
        q0 += __shfl_xor_sync(0xffffffffu, q0, off);
        s1 += __shfl_xor_sync(0xffffffffu, s1, off);
        q1 += __shfl_xor_sync(0xffffffffu, q1, off);
    }
    if (tg == 0) {
        redS[t0][dg] = s0; redQ[t0][dg] = q0;
        redS[t1][dg] = s1; redQ[t1][dg] = q1;
    }
    __syncthreads();

    if (tid < TT) {
        float sm = 0.f, sq = 0.f;
        #pragma unroll
        for (int wi = 0; wi < 8; wi++) { sm += redS[tid][wi]; sq += redQ[tid][wi]; }
        const float mn = sm * (1.0f / (float)EDIM);
        const float vr = sq * (1.0f / (float)EDIM) - mn * mn;
        meanv[tid] = mn;
        rstdv[tid] = rsqrtf(vr + 0.001f);
    }
    __syncthreads();

    const float mn0 = meanv[t0], rs0 = rstdv[t0];
    const float mn1 = meanv[t1], rs1 = rstdv[t1];

    if (!is_mask) {
        float* o0 = out + ((size_t)b * TOKENS + (size_t)tile * TT + t0) * EDIM;
        float* o1 = out + ((size_t)b * TOKENS + (size_t)tile * TT + t1) * EDIM;
        #pragma unroll
        for (int j = 0; j < NJ; j++) {
            const int e = ebase + 8 * j;
            const float2 gm = *(const float2*)(gamma + e);
            const float2 bt = *(const float2*)(beta + e);
            float2 r0v, r1v;
            r0v.x = (acc[j][0] - mn0) * rs0 * gm.x + bt.x;
            r0v.y = (acc[j][1] - mn0) * rs0 * gm.y + bt.y;
            r1v.x = (acc[j][2] - mn1) * rs1 * gm.x + bt.x;
            r1v.y = (acc[j][3] - mn1) * rs1 * gm.y + bt.y;
            *(float2*)(o0 + e) = r0v;
            *(float2*)(o1 + e) = r1v;
        }
    } else {
        float* o0 = out + ((size_t)UNMASKN + (size_t)tile * TT + t0) * EDIM;
        float* o1 = out + ((size_t)UNMASKN + (size_t)tile * TT + t1) * EDIM;
        const size_t bstride = (size_t)TOKENS * EDIM;
        #pragma unroll
        for (int j = 0; j < NJ; j++) {
            const int e = ebase + 8 * j;
            const float2 gm = *(const float2*)(gamma + e);
            const float2 bt = *(const float2*)(beta + e);
            float2 r0v, r1v;
            r0v.x = (acc[j][0] - mn0) * rs0 * gm.x + bt.x;
            r0v.y = (acc[j][1] - mn0) * rs0 * gm.y + bt.y;
            r1v.x = (acc[j][2] - mn1) * rs1 * gm.x + bt.x;
            r1v.y = (acc[j][3] - mn1) * rs1 * gm.y + bt.y;
            #pragma unroll
            for (int bb = 0; bb < BATCH; bb++) {
                *(float2*)(o0 + bb * bstride + e) = r0v;
                *(float2*)(o1 + bb * bstride + e) = r1v;
            }
        }
    }
}

extern "C" void kernel_launch(void* const* d_in, const int* in_sizes, int n_in,
                              void* d_out, int out_size) {
    const float* x     = (const float*)d_in[0];
    const float* W     = (const float*)d_in[1];
    const float* bias  = (const float*)d_in[2];
    const float* mtok  = (const float*)d_in[3];
    const float* gamma = (const float*)d_in[4];
    const float* beta  = (const float*)d_in[5];
    const int*   perm  = (const int*)d_in[6];
    float* out = (float*)d_out;

    const long long main_elems = (long long)BATCH * TOKENS * EDIM;  // 42,467,328
    const long long extra = (long long)out_size - main_elems;       // expected 10368 (mask_idx)
    const int n_tail = extra > 0 ? (int)extra : 0;
    const int tail_blocks = (n_tail + 255) / 256;

    // idempotent, non-stream host call (no allocation): raise dynamic smem cap
    cudaFuncSetAttribute(embed_kernel,
                         cudaFuncAttributeMaxDynamicSharedMemorySize, SMEM_TOTAL);

    init_kernel<<<24 + 288 + tail_blocks, 256>>>(W, perm, out + main_elems, n_tail);

    embed_kernel<<<BATCH * UT + MT, NTHREADS, SMEM_TOTAL>>>(
        x, bias, mtok, gamma, beta, perm, out);
}